// round 7
// baseline (speedup 1.0000x reference)
#include <cuda_runtime.h>
#include <cuda_bf16.h>
#include <math_constants.h>

// Problem constants
#define NROWS 8192
#define DDIM  128
#define NCLS  10
#define GAPV  0.4f

// Tiling
#define TM 128
#define TN 128
#define KB 32
#define APAD 132   // row stride (floats) for smem tiles; 132*4=528 bytes, 16B aligned

// Scratch (device globals: no allocation allowed)
__device__ float    g_sq[NROWS];
__device__ unsigned g_ap[NROWS];   // max clamped squared dist over same-class (uint-ordered float)
__device__ unsigned g_an[NROWS];   // min clamped squared dist over diff-class
__device__ int      g_cls[NROWS];  // targets normalized to int32

// ---------------------------------------------------------------------------
// Kernel 0: normalize targets to int32, robust to the buffer actually being
// int32 (JAX demotes int64 without x64) or genuine int64.
// Detection: probe odd 32-bit words 1..127. For little-endian int64 with
// class values 0..9 these are ALL high words == 0. For an int32 buffer they
// are targets[1,3,...,127]; all-zero has probability 0.1^64 ~ 0.
// ---------------------------------------------------------------------------
__global__ void classes_kernel(const int* __restrict__ tgt32) {
    __shared__ int s_stride;
    int tid = threadIdx.x;
    if (tid == 0) {
        int any = 0;
        #pragma unroll
        for (int i = 1; i < 128; i += 2) any |= tgt32[i];
        s_stride = (any == 0) ? 2 : 1;   // 2 => int64 layout, read low words
    }
    __syncthreads();
    int stride = s_stride;
    for (int i = tid; i < NROWS; i += 1024)
        g_cls[i] = tgt32[i * stride];
}

// ---------------------------------------------------------------------------
// Kernel 1: per-row squared norms + (re)init of reduction buffers.
// One warp per row, float4 loads. grid = NROWS/8 blocks of 256 threads.
// ---------------------------------------------------------------------------
__global__ void row_stats_kernel(const float* __restrict__ X) {
    int row  = blockIdx.x * 8 + (threadIdx.x >> 5);
    int lane = threadIdx.x & 31;
    const float4 v = *reinterpret_cast<const float4*>(X + (size_t)row * DDIM + lane * 4);
    float s = v.x * v.x + v.y * v.y + v.z * v.z + v.w * v.w;
    #pragma unroll
    for (int m = 16; m > 0; m >>= 1)
        s += __shfl_xor_sync(0xffffffffu, s, m);
    if (lane == 0) {
        g_sq[row] = s;
        g_ap[row] = 0u;                       // acts as -inf for clamped d2 (>=1e-12)
        g_an[row] = 0x7f800000u;              // +inf
    }
}

// ---------------------------------------------------------------------------
// Kernel 2: tiled Gram + fused distance/mask/row-reduce epilogue.
// Block = 256 threads (16x16), 128x128 tile, 8x8 per-thread micro-tile.
// grid = (64 col tiles, 64 row tiles).
// ---------------------------------------------------------------------------
__global__ __launch_bounds__(256, 2)
void pair_tiles_kernel(const float* __restrict__ X) {
    __shared__ __align__(16) float As[KB][APAD];
    __shared__ __align__(16) float Bs[KB][APAD];
    __shared__ float ssq_r[TM], ssq_c[TN];
    __shared__ int   cls_r[TM], cls_c[TN];

    const int tid = threadIdx.x;
    const int tx  = tid & 15;
    const int ty  = tid >> 4;
    const int row0 = blockIdx.y * TM;
    const int col0 = blockIdx.x * TN;

    // stage per-row/col norms + classes
    if (tid < TM) {
        ssq_r[tid] = g_sq[row0 + tid];
        cls_r[tid] = g_cls[row0 + tid];
    } else {
        int j = tid - TM;
        ssq_c[j] = g_sq[col0 + j];
        cls_c[j] = g_cls[col0 + j];
    }

    float acc[8][8];
    #pragma unroll
    for (int i = 0; i < 8; i++)
        #pragma unroll
        for (int j = 0; j < 8; j++)
            acc[i][j] = 0.0f;

    #pragma unroll
    for (int kc = 0; kc < DDIM / KB; kc++) {
        // load A chunk [TM x KB] transposed -> As[k][m]; same for B
        #pragma unroll
        for (int it = 0; it < 4; it++) {
            int idx = tid + it * 256;
            int r   = idx >> 3;        // 0..127
            int c4  = idx & 7;         // 0..7 (float4 index)
            float4 va = *reinterpret_cast<const float4*>(
                X + (size_t)(row0 + r) * DDIM + kc * KB + c4 * 4);
            As[c4 * 4 + 0][r] = va.x;
            As[c4 * 4 + 1][r] = va.y;
            As[c4 * 4 + 2][r] = va.z;
            As[c4 * 4 + 3][r] = va.w;
            float4 vb = *reinterpret_cast<const float4*>(
                X + (size_t)(col0 + r) * DDIM + kc * KB + c4 * 4);
            Bs[c4 * 4 + 0][r] = vb.x;
            Bs[c4 * 4 + 1][r] = vb.y;
            Bs[c4 * 4 + 2][r] = vb.z;
            Bs[c4 * 4 + 3][r] = vb.w;
        }
        __syncthreads();

        #pragma unroll
        for (int k = 0; k < KB; k++) {
            float4 a0 = *reinterpret_cast<const float4*>(&As[k][ty * 4]);
            float4 a1 = *reinterpret_cast<const float4*>(&As[k][64 + ty * 4]);
            float4 b0 = *reinterpret_cast<const float4*>(&Bs[k][tx * 4]);
            float4 b1 = *reinterpret_cast<const float4*>(&Bs[k][64 + tx * 4]);
            float a[8] = {a0.x, a0.y, a0.z, a0.w, a1.x, a1.y, a1.z, a1.w};
            float b[8] = {b0.x, b0.y, b0.z, b0.w, b1.x, b1.y, b1.z, b1.w};
            #pragma unroll
            for (int i = 0; i < 8; i++)
                #pragma unroll
                for (int j = 0; j < 8; j++)
                    acc[i][j] = fmaf(a[i], b[j], acc[i][j]);
        }
        __syncthreads();
    }

    // Epilogue: clamped squared distance + class masks + row reduce.
    #pragma unroll
    for (int i = 0; i < 8; i++) {
        int rm = (i < 4) ? (ty * 4 + i) : (64 + ty * 4 + (i - 4));
        float sqr = ssq_r[rm];
        int   cr  = cls_r[rm];
        float apv = 0.0f;
        float anv = CUDART_INF_F;
        #pragma unroll
        for (int j = 0; j < 8; j++) {
            int cn = (j < 4) ? (tx * 4 + j) : (64 + tx * 4 + (j - 4));
            float d2 = fmaxf(fmaf(-2.0f, acc[i][j], sqr + ssq_c[cn]), 1e-12f);
            bool same = (cr == cls_c[cn]);
            apv = fmaxf(apv, same ? d2 : 0.0f);
            anv = fminf(anv, same ? CUDART_INF_F : d2);
        }
        #pragma unroll
        for (int m = 1; m < 16; m <<= 1) {
            apv = fmaxf(apv, __shfl_xor_sync(0xffffffffu, apv, m));
            anv = fminf(anv, __shfl_xor_sync(0xffffffffu, anv, m));
        }
        if (tx == 0) {
            atomicMax(&g_ap[row0 + rm], __float_as_uint(apv));
            atomicMin(&g_an[row0 + rm], __float_as_uint(anv));
        }
    }
}

// ---------------------------------------------------------------------------
// Kernel 3: confusion detection + masked mean. Single block.
// ---------------------------------------------------------------------------
__global__ void finalize_kernel(const float* __restrict__ pred,
                                float* __restrict__ out) {
    __shared__ float s_sum[1024];
    __shared__ float s_cnt[1024];
    int tid = threadIdx.x;
    float sum = 0.0f, cnt = 0.0f;

    for (int i = tid; i < NROWS; i += 1024) {
        // softmax top-2 + argmax over 10 logits
        const float* pr = pred + (size_t)i * NCLS;
        float l[NCLS];
        float mx = -CUDART_INF_F;
        #pragma unroll
        for (int c = 0; c < NCLS; c++) { l[c] = pr[c]; mx = fmaxf(mx, l[c]); }
        float s = 0.0f;
        #pragma unroll
        for (int c = 0; c < NCLS; c++) { l[c] = __expf(l[c] - mx); s += l[c]; }
        float inv = 1.0f / s;
        float v1 = -1.0f, v2 = -1.0f;
        int i1 = 0;
        #pragma unroll
        for (int c = 0; c < NCLS; c++) {
            float p = l[c] * inv;
            if (p > v1) { v2 = v1; v1 = p; i1 = c; }
            else if (p > v2) { v2 = p; }
        }
        bool confuse = ((v1 - v2) <= GAPV) || (i1 != g_cls[i]);

        float ap = sqrtf(__uint_as_float(g_ap[i]));
        float an = sqrtf(__uint_as_float(g_an[i]));
        float per = fmaxf(ap - an, 0.0f);   // MARGIN = 0
        if (confuse) { sum += per; cnt += 1.0f; }
    }

    s_sum[tid] = sum;
    s_cnt[tid] = cnt;
    __syncthreads();
    for (int ofs = 512; ofs > 0; ofs >>= 1) {
        if (tid < ofs) {
            s_sum[tid] += s_sum[tid + ofs];
            s_cnt[tid] += s_cnt[tid + ofs];
        }
        __syncthreads();
    }
    if (tid == 0) {
        float c = s_cnt[0];
        out[0] = (c > 0.0f) ? (s_sum[0] / c) : 0.0f;
    }
}

// ---------------------------------------------------------------------------
extern "C" void kernel_launch(void* const* d_in, const int* in_sizes, int n_in,
                              void* d_out, int out_size) {
    const float* X    = (const float*)d_in[0];      // [8192,128] f32
    const float* pred = (const float*)d_in[1];      // [8192,10]  f32
    const int*   tgt  = (const int*)d_in[2];        // [8192] i32 (or i64 low/high pairs)
    float* out = (float*)d_out;

    classes_kernel<<<1, 1024>>>(tgt);
    row_stats_kernel<<<NROWS / 8, 256>>>(X);
    dim3 grid(NROWS / TN, NROWS / TM);
    pair_tiles_kernel<<<grid, 256>>>(X);
    finalize_kernel<<<1, 1024>>>(pred, out);
}

// round 10
// speedup vs baseline: 2.8342x; 2.8342x over previous
#include <cuda_runtime.h>
#include <cuda_bf16.h>
#include <math_constants.h>
#include <cstdint>

#define NROWS 8192
#define DDIM  128
#define NCLS  10
#define GAPV  0.4f
#define TILE_BYTES 32768   // 128 rows x 256 bytes (128 bf16)

// -------- device scratch (no allocation allowed) ---------------------------
__device__ __align__(128) unsigned char g_H_img[NROWS * 256]; // 2MB swizzled bf16 hi
__device__ __align__(128) unsigned char g_L_img[NROWS * 256]; // 2MB swizzled bf16 lo
__device__ float    g_sq[NROWS];
__device__ unsigned g_ap[NROWS];
__device__ unsigned g_an[NROWS];
__device__ int      g_cls[NROWS];
__device__ float    g_part[64];

// -------- helpers ----------------------------------------------------------
__device__ __forceinline__ unsigned smem_u32(const void* p) {
    unsigned a;
    asm("{ .reg .u64 t; cvta.to.shared.u64 t, %1; cvt.u32.u64 %0, t; }" : "=r"(a) : "l"(p));
    return a;
}
__device__ __forceinline__ void mbar_init(unsigned a, unsigned cnt) {
    asm volatile("mbarrier.init.shared.b64 [%0], %1;" :: "r"(a), "r"(cnt) : "memory");
}
__device__ __forceinline__ void mbar_expect_tx(unsigned a, unsigned bytes) {
    asm volatile("mbarrier.arrive.expect_tx.shared.b64 _, [%0], %1;" :: "r"(a), "r"(bytes) : "memory");
}
__device__ __forceinline__ void mbar_wait(unsigned a, unsigned ph) {
    asm volatile(
        "{\n\t.reg .pred P;\n\t"
        "W_%=:\n\t"
        "mbarrier.try_wait.parity.acquire.cta.shared::cta.b64 P, [%0], %1, 0x989680;\n\t"
        "@P bra.uni D_%=;\n\t"
        "bra.uni W_%=;\n\t"
        "D_%=:\n\t}"
        :: "r"(a), "r"(ph) : "memory");
}
__device__ __forceinline__ void bulk_g2s(unsigned dst, const void* src, unsigned bytes, unsigned mbar) {
    asm volatile(
        "cp.async.bulk.shared::cluster.global.mbarrier::complete_tx::bytes [%0], [%1], %2, [%3];"
        :: "r"(dst), "l"(src), "r"(bytes), "r"(mbar) : "memory");
}
__device__ __forceinline__ void ldsm4(unsigned* r, unsigned addr) {
    asm volatile("ldmatrix.sync.aligned.m8n8.x4.shared.b16 {%0,%1,%2,%3}, [%4];"
        : "=r"(r[0]), "=r"(r[1]), "=r"(r[2]), "=r"(r[3]) : "r"(addr));
}
__device__ __forceinline__ void mma16816(float* c, const unsigned* a, unsigned b0, unsigned b1) {
    asm volatile(
        "mma.sync.aligned.m16n8k16.row.col.f32.bf16.bf16.f32 "
        "{%0,%1,%2,%3}, {%4,%5,%6,%7}, {%8,%9}, {%0,%1,%2,%3};"
        : "+f"(c[0]), "+f"(c[1]), "+f"(c[2]), "+f"(c[3])
        : "r"(a[0]), "r"(a[1]), "r"(a[2]), "r"(a[3]), "r"(b0), "r"(b1));
}

// swizzled byte offset inside one 128x256B tile image (r: 0..127, kbyte: 0..255)
__device__ __forceinline__ unsigned tile_off(int r, int kbyte) {
    return (unsigned)r * 256u + ((unsigned)kbyte ^ (((unsigned)r & 7u) << 4));
}

// ---------------------------------------------------------------------------
// Kernel 0: normalize targets (int32 vs int64-low-word autodetect).
// ---------------------------------------------------------------------------
__global__ void classes_kernel(const int* __restrict__ tgt32) {
    __shared__ int s_stride;
    int tid = threadIdx.x;
    if (tid == 0) {
        int any = 0;
        #pragma unroll
        for (int i = 1; i < 128; i += 2) any |= tgt32[i];
        s_stride = (any == 0) ? 2 : 1;
    }
    __syncthreads();
    int stride = s_stride;
    for (int i = blockIdx.x * 1024 + tid; i < NROWS; i += gridDim.x * 1024)
        g_cls[i] = tgt32[i * stride];
}

// ---------------------------------------------------------------------------
// Kernel 1: split X -> bf16 H/L swizzled images; row norms; reset buffers.
// One warp per row. 1024 blocks x 256 threads.
// ---------------------------------------------------------------------------
__global__ void convert_kernel(const float* __restrict__ X) {
    int wid = threadIdx.x >> 5, lane = threadIdx.x & 31;
    int row = blockIdx.x * 8 + wid;
    int k4  = lane * 4;

    float4 v = *reinterpret_cast<const float4*>(X + (size_t)row * DDIM + k4);
    float s = v.x * v.x + v.y * v.y + v.z * v.z + v.w * v.w;
    #pragma unroll
    for (int m = 16; m > 0; m >>= 1) s += __shfl_xor_sync(0xffffffffu, s, m);
    if (lane == 0) {
        g_sq[row] = s;
        g_ap[row] = 0u;
        g_an[row] = 0x7f800000u;
    }

    __nv_bfloat16 h0 = __float2bfloat16(v.x), h1 = __float2bfloat16(v.y);
    __nv_bfloat16 h2 = __float2bfloat16(v.z), h3 = __float2bfloat16(v.w);
    __nv_bfloat16 l0 = __float2bfloat16(v.x - __bfloat162float(h0));
    __nv_bfloat16 l1 = __float2bfloat16(v.y - __bfloat162float(h1));
    __nv_bfloat16 l2 = __float2bfloat16(v.z - __bfloat162float(h2));
    __nv_bfloat16 l3 = __float2bfloat16(v.w - __bfloat162float(h3));

    uint2 hp, lp;
    hp.x = ((unsigned)__bfloat16_as_ushort(h1) << 16) | __bfloat16_as_ushort(h0);
    hp.y = ((unsigned)__bfloat16_as_ushort(h3) << 16) | __bfloat16_as_ushort(h2);
    lp.x = ((unsigned)__bfloat16_as_ushort(l1) << 16) | __bfloat16_as_ushort(l0);
    lp.y = ((unsigned)__bfloat16_as_ushort(l3) << 16) | __bfloat16_as_ushort(l2);

    size_t base = (size_t)(row >> 7) * TILE_BYTES + tile_off(row & 127, k4 * 2);
    *reinterpret_cast<uint2*>(g_H_img + base) = hp;
    *reinterpret_cast<uint2*>(g_L_img + base) = lp;
}

// ---------------------------------------------------------------------------
// Kernel 2: persistent HMMA Gram + fused epilogue.
// Grid (64 col-tiles, 2 groups) = 128 CTAs (one wave). 256 threads.
// B tiles (H+L) resident; A tiles double-buffered via cp.async.bulk.
// Warp grid: 4 (m) x 2 (n); each warp 32x64 of the 128x128 tile.
// 3 split-bf16 terms: HH + HL + LH (LL dropped, ~2^-18 rel).
// ---------------------------------------------------------------------------
__global__ __launch_bounds__(256, 1) void gram_kernel() {
    extern __shared__ __align__(128) unsigned char dsm[];
    __shared__ __align__(8) unsigned long long s_mbar[2];
    __shared__ float s_sqc[128];
    __shared__ int   s_clsc[128];

    const int tid = threadIdx.x, lane = tid & 31, w = tid >> 5;
    const int warp_m = w & 3, warp_n = w >> 2;
    const int cx  = blockIdx.x;
    const int grp = blockIdx.y;
    const int col0 = cx * 128;

    const unsigned sbase = smem_u32(dsm);
    // layout: A stage b: sbase + b*65536 (H), +32768 (L); B: +131072 (H), +163840 (L)

    if (tid == 0) { mbar_init(smem_u32(&s_mbar[0]), 1); mbar_init(smem_u32(&s_mbar[1]), 1); }

    // resident B tiles + col-side stats
    {
        const uint4* sh = reinterpret_cast<const uint4*>(g_H_img + (size_t)cx * TILE_BYTES);
        const uint4* sl = reinterpret_cast<const uint4*>(g_L_img + (size_t)cx * TILE_BYTES);
        uint4* dh = reinterpret_cast<uint4*>(dsm + 131072);
        uint4* dl = reinterpret_cast<uint4*>(dsm + 163840);
        #pragma unroll
        for (int i = 0; i < 8; i++) {
            dh[tid + i * 256] = sh[tid + i * 256];
            dl[tid + i * 256] = sl[tid + i * 256];
        }
        if (tid < 128) { s_sqc[tid] = g_sq[col0 + tid]; s_clsc[tid] = g_cls[col0 + tid]; }
    }
    __syncthreads();

    unsigned mb[2] = { smem_u32(&s_mbar[0]), smem_u32(&s_mbar[1]) };
    unsigned ph[2] = {0, 0};

    if (tid == 0) {
        int yt0 = grp * 32;
        mbar_expect_tx(mb[0], 2 * TILE_BYTES);
        bulk_g2s(sbase,         g_H_img + (size_t)yt0 * TILE_BYTES, TILE_BYTES, mb[0]);
        bulk_g2s(sbase + 32768, g_L_img + (size_t)yt0 * TILE_BYTES, TILE_BYTES, mb[0]);
    }

    // per-lane ldmatrix address components
    const int aR = lane & 15;                       // A: row within 16
    const int aK = (lane >> 4) * 16;                // A: k-byte half
    const int bN = (lane & 7) + ((lane >> 4) << 3); // B: n-row within 16 (2 n8 tiles)
    const int bK = ((lane >> 3) & 1) * 16;          // B: k-byte half
    unsigned aoff[2], asw[2];
    #pragma unroll
    for (int mi = 0; mi < 2; mi++) {
        int r = warp_m * 32 + mi * 16 + aR;
        aoff[mi] = (unsigned)r * 256u;
        asw[mi]  = ((unsigned)r & 7u) << 4;
    }
    unsigned boff[4], bsw[4];
    #pragma unroll
    for (int p = 0; p < 4; p++) {
        int r = warp_n * 64 + p * 16 + bN;
        boff[p] = (unsigned)r * 256u;
        bsw[p]  = ((unsigned)r & 7u) << 4;
    }
    const int qr = lane >> 2;
    const int qc = (lane & 3) * 2;

    const unsigned BH = sbase + 131072u, BL = sbase + 163840u;

    for (int t = 0; t < 32; ++t) {
        const int b = t & 1;
        mbar_wait(mb[b], ph[b]); ph[b] ^= 1;

        if (tid == 0 && t + 1 < 32) {
            const int nb = 1 - b;
            const int ytn = grp * 32 + t + 1;
            mbar_expect_tx(mb[nb], 2 * TILE_BYTES);
            bulk_g2s(sbase + nb * 65536u,          g_H_img + (size_t)ytn * TILE_BYTES, TILE_BYTES, mb[nb]);
            bulk_g2s(sbase + nb * 65536u + 32768u, g_L_img + (size_t)ytn * TILE_BYTES, TILE_BYTES, mb[nb]);
        }

        const unsigned AH = sbase + (unsigned)b * 65536u, AL = AH + 32768u;

        float acc[2][8][4];
        #pragma unroll
        for (int mi = 0; mi < 2; mi++)
            #pragma unroll
            for (int ni = 0; ni < 8; ni++)
                #pragma unroll
                for (int x = 0; x < 4; x++) acc[mi][ni][x] = 0.0f;

        #pragma unroll
        for (int ks = 0; ks < 8; ++ks) {
            const unsigned kbA = (unsigned)(ks * 32 + aK);
            const unsigned kbB = (unsigned)(ks * 32 + bK);
            unsigned ah[2][4], al[2][4], bh[4][4], bl[4][4];
            #pragma unroll
            for (int mi = 0; mi < 2; mi++) {
                ldsm4(ah[mi], AH + aoff[mi] + (kbA ^ asw[mi]));
                ldsm4(al[mi], AL + aoff[mi] + (kbA ^ asw[mi]));
            }
            #pragma unroll
            for (int p = 0; p < 4; p++) {
                ldsm4(bh[p], BH + boff[p] + (kbB ^ bsw[p]));
                ldsm4(bl[p], BL + boff[p] + (kbB ^ bsw[p]));
            }
            #pragma unroll
            for (int mi = 0; mi < 2; mi++)
                #pragma unroll
                for (int ni = 0; ni < 8; ni++) {
                    const int p = ni >> 1, s = (ni & 1) * 2;
                    mma16816(acc[mi][ni], ah[mi], bh[p][s], bh[p][s + 1]); // H.H
                    mma16816(acc[mi][ni], ah[mi], bl[p][s], bl[p][s + 1]); // H.L
                    mma16816(acc[mi][ni], al[mi], bh[p][s], bh[p][s + 1]); // L.H
                }
        }

        // fused epilogue: m = (sqc - 2*dot); row max/min with class masks
        const int row0 = (grp * 32 + t) * 128;
        #pragma unroll
        for (int mi = 0; mi < 2; mi++) {
            const int rlo = row0 + warp_m * 32 + mi * 16 + qr;
            const int rhi = rlo + 8;
            const int crlo = g_cls[rlo], crhi = g_cls[rhi];
            float apl = -CUDART_INF_F, anl = CUDART_INF_F;
            float aph = -CUDART_INF_F, anh = CUDART_INF_F;
            #pragma unroll
            for (int ni = 0; ni < 8; ni++) {
                const int cl = warp_n * 64 + ni * 8 + qc;
                const float s0 = s_sqc[cl], s1 = s_sqc[cl + 1];
                const int   k0 = s_clsc[cl], k1 = s_clsc[cl + 1];
                const float v00 = fmaf(-2.0f, acc[mi][ni][0], s0);
                const float v01 = fmaf(-2.0f, acc[mi][ni][1], s1);
                const float v10 = fmaf(-2.0f, acc[mi][ni][2], s0);
                const float v11 = fmaf(-2.0f, acc[mi][ni][3], s1);
                const bool m0lo = (k0 == crlo), m1lo = (k1 == crlo);
                const bool m0hi = (k0 == crhi), m1hi = (k1 == crhi);
                apl = fmaxf(apl, m0lo ? v00 : -CUDART_INF_F);
                apl = fmaxf(apl, m1lo ? v01 : -CUDART_INF_F);
                anl = fminf(anl, m0lo ? CUDART_INF_F : v00);
                anl = fminf(anl, m1lo ? CUDART_INF_F : v01);
                aph = fmaxf(aph, m0hi ? v10 : -CUDART_INF_F);
                aph = fmaxf(aph, m1hi ? v11 : -CUDART_INF_F);
                anh = fminf(anh, m0hi ? CUDART_INF_F : v10);
                anh = fminf(anh, m1hi ? CUDART_INF_F : v11);
            }
            #pragma unroll
            for (int m = 1; m < 4; m <<= 1) {
                apl = fmaxf(apl, __shfl_xor_sync(0xffffffffu, apl, m));
                anl = fminf(anl, __shfl_xor_sync(0xffffffffu, anl, m));
                aph = fmaxf(aph, __shfl_xor_sync(0xffffffffu, aph, m));
                anh = fminf(anh, __shfl_xor_sync(0xffffffffu, anh, m));
            }
            if ((lane & 3) == 0) {
                const float sqlo = g_sq[rlo], sqhi = g_sq[rhi];
                atomicMax(&g_ap[rlo], __float_as_uint(fmaxf(sqlo + apl, 1e-12f)));
                atomicMin(&g_an[rlo], __float_as_uint(fmaxf(sqlo + anl, 1e-12f)));
                atomicMax(&g_ap[rhi], __float_as_uint(fmaxf(sqhi + aph, 1e-12f)));
                atomicMin(&g_an[rhi], __float_as_uint(fmaxf(sqhi + anh, 1e-12f)));
            }
        }
        __syncthreads();   // everyone done reading A buf b before it is refilled
    }
}

// ---------------------------------------------------------------------------
// Kernel 3: per-row confusion + partial sums. 32 blocks x 256.
// ---------------------------------------------------------------------------
__global__ void confuse_kernel(const float* __restrict__ pred) {
    __shared__ float s_s[8], s_c[8];
    int i = blockIdx.x * 256 + threadIdx.x;

    const float* pr = pred + (size_t)i * NCLS;
    float l[NCLS];
    float mx = -CUDART_INF_F;
    #pragma unroll
    for (int c = 0; c < NCLS; c++) { l[c] = pr[c]; mx = fmaxf(mx, l[c]); }
    float s = 0.0f;
    #pragma unroll
    for (int c = 0; c < NCLS; c++) { l[c] = __expf(l[c] - mx); s += l[c]; }
    float inv = 1.0f / s;
    float v1 = -1.0f, v2 = -1.0f;
    int i1 = 0;
    #pragma unroll
    for (int c = 0; c < NCLS; c++) {
        float p = l[c] * inv;
        if (p > v1) { v2 = v1; v1 = p; i1 = c; }
        else if (p > v2) { v2 = p; }
    }
    bool confuse = ((v1 - v2) <= GAPV) || (i1 != g_cls[i]);

    float ap = sqrtf(__uint_as_float(g_ap[i]));
    float an = sqrtf(__uint_as_float(g_an[i]));
    float per = fmaxf(ap - an, 0.0f);
    float sum = confuse ? per : 0.0f;
    float cnt = confuse ? 1.0f : 0.0f;

    #pragma unroll
    for (int m = 16; m > 0; m >>= 1) {
        sum += __shfl_xor_sync(0xffffffffu, sum, m);
        cnt += __shfl_xor_sync(0xffffffffu, cnt, m);
    }
    int wid = threadIdx.x >> 5, lane = threadIdx.x & 31;
    if (lane == 0) { s_s[wid] = sum; s_c[wid] = cnt; }
    __syncthreads();
    if (threadIdx.x == 0) {
        float ts = 0.0f, tc = 0.0f;
        #pragma unroll
        for (int w2 = 0; w2 < 8; w2++) { ts += s_s[w2]; tc += s_c[w2]; }
        g_part[blockIdx.x * 2]     = ts;
        g_part[blockIdx.x * 2 + 1] = tc;
    }
}

__global__ void final_kernel(float* __restrict__ out) {
    float s = 0.0f, c = 0.0f;
    #pragma unroll
    for (int b = 0; b < 32; b++) { s += g_part[b * 2]; c += g_part[b * 2 + 1]; }
    out[0] = (c > 0.0f) ? (s / c) : 0.0f;
}

// ---------------------------------------------------------------------------
extern "C" void kernel_launch(void* const* d_in, const int* in_sizes, int n_in,
                              void* d_out, int out_size) {
    const float* X    = (const float*)d_in[0];
    const float* pred = (const float*)d_in[1];
    const int*   tgt  = (const int*)d_in[2];
    float* out = (float*)d_out;

    static int smem_set = 0;
    const int SMEM_DYN = 196608;   // 2 x 64KB A stages + 64KB resident B
    if (!smem_set) {
        cudaFuncSetAttribute(gram_kernel,
                             cudaFuncAttributeMaxDynamicSharedMemorySize, SMEM_DYN);
        smem_set = 1;
    }

    classes_kernel<<<8, 1024>>>(tgt);
    convert_kernel<<<NROWS / 8, 256>>>(X);
    gram_kernel<<<dim3(64, 2), 256, SMEM_DYN>>>();
    confuse_kernel<<<32, 256>>>(pred);
    final_kernel<<<1, 1>>>(out);
}

// round 11
// speedup vs baseline: 4.0761x; 1.4382x over previous
#include <cuda_runtime.h>
#include <cuda_bf16.h>
#include <math_constants.h>
#include <cstdint>

#define NROWS 8192
#define DDIM  128
#define NCLS  10
#define GAPV  0.4f
#define NTILE 64
#define SUB   16384          // one 128-row x 64-k bf16 swizzled sub-image
#define NUNITS 2080          // 64*65/2 upper-triangular tiles
#define NCTA  148
#define STAGE 65536          // A_H,A_L,B_H,B_L sub-images (4 x 16KB)
#define NSTG  3

// -------- device scratch (no allocation allowed) ---------------------------
// image layout: [tile][khalf][row 0..127][128 bytes, 16B-chunk swizzled]
__device__ __align__(128) unsigned char g_H_img[NROWS * 256];
__device__ __align__(128) unsigned char g_L_img[NROWS * 256];
__device__ float    g_sq[NROWS];
__device__ unsigned g_ap[NROWS];
__device__ unsigned g_an[NROWS];
__device__ int      g_cls[NROWS];
__device__ float    g_part[64];

// -------- helpers ----------------------------------------------------------
__device__ __forceinline__ unsigned smem_u32(const void* p) {
    unsigned a;
    asm("{ .reg .u64 t; cvta.to.shared.u64 t, %1; cvt.u32.u64 %0, t; }" : "=r"(a) : "l"(p));
    return a;
}
__device__ __forceinline__ void mbar_init(unsigned a, unsigned cnt) {
    asm volatile("mbarrier.init.shared.b64 [%0], %1;" :: "r"(a), "r"(cnt) : "memory");
}
__device__ __forceinline__ void mbar_arrive(unsigned a) {
    asm volatile("mbarrier.arrive.shared.b64 _, [%0];" :: "r"(a) : "memory");
}
__device__ __forceinline__ void mbar_expect_tx(unsigned a, unsigned bytes) {
    asm volatile("mbarrier.arrive.expect_tx.shared.b64 _, [%0], %1;" :: "r"(a), "r"(bytes) : "memory");
}
__device__ __forceinline__ void mbar_wait(unsigned a, unsigned ph) {
    asm volatile(
        "{\n\t.reg .pred P;\n\t"
        "W_%=:\n\t"
        "mbarrier.try_wait.parity.acquire.cta.shared::cta.b64 P, [%0], %1, 0x989680;\n\t"
        "@P bra.uni D_%=;\n\t"
        "bra.uni W_%=;\n\t"
        "D_%=:\n\t}"
        :: "r"(a), "r"(ph) : "memory");
}
__device__ __forceinline__ void bulk_g2s(unsigned dst, const void* src, unsigned bytes, unsigned mbar) {
    asm volatile(
        "cp.async.bulk.shared::cluster.global.mbarrier::complete_tx::bytes [%0], [%1], %2, [%3];"
        :: "r"(dst), "l"(src), "r"(bytes), "r"(mbar) : "memory");
}
__device__ __forceinline__ void ldsm4(unsigned* r, unsigned addr) {
    asm volatile("ldmatrix.sync.aligned.m8n8.x4.shared.b16 {%0,%1,%2,%3}, [%4];"
        : "=r"(r[0]), "=r"(r[1]), "=r"(r[2]), "=r"(r[3]) : "r"(addr));
}
__device__ __forceinline__ void mma16816(float* c, const unsigned* a, unsigned b0, unsigned b1) {
    asm volatile(
        "mma.sync.aligned.m16n8k16.row.col.f32.bf16.bf16.f32 "
        "{%0,%1,%2,%3}, {%4,%5,%6,%7}, {%8,%9}, {%0,%1,%2,%3};"
        : "+f"(c[0]), "+f"(c[1]), "+f"(c[2]), "+f"(c[3])
        : "r"(a[0]), "r"(a[1]), "r"(a[2]), "r"(a[3]), "r"(b0), "r"(b1));
}
// swizzled byte offset inside one 128x128B sub-image
__device__ __forceinline__ unsigned sub_off(int r, int kbyte) {
    return (unsigned)r * 128u + ((unsigned)kbyte ^ (((unsigned)r & 7u) << 4));
}

// ---------------------------------------------------------------------------
// Kernel 0: normalize targets (int32 vs int64-low-word autodetect).
// ---------------------------------------------------------------------------
__global__ void classes_kernel(const int* __restrict__ tgt32) {
    __shared__ int s_stride;
    int tid = threadIdx.x;
    if (tid == 0) {
        int any = 0;
        #pragma unroll
        for (int i = 1; i < 128; i += 2) any |= tgt32[i];
        s_stride = (any == 0) ? 2 : 1;
    }
    __syncthreads();
    int stride = s_stride;
    for (int i = blockIdx.x * 1024 + tid; i < NROWS; i += gridDim.x * 1024)
        g_cls[i] = tgt32[i * stride];
}

// ---------------------------------------------------------------------------
// Kernel 1: split X -> bf16 H/L khalf-split swizzled images; row norms; reset.
// ---------------------------------------------------------------------------
__global__ void convert_kernel(const float* __restrict__ X) {
    int wid = threadIdx.x >> 5, lane = threadIdx.x & 31;
    int row = blockIdx.x * 8 + wid;
    int k4  = lane * 4;

    float4 v = *reinterpret_cast<const float4*>(X + (size_t)row * DDIM + k4);
    float s = v.x * v.x + v.y * v.y + v.z * v.z + v.w * v.w;
    #pragma unroll
    for (int m = 16; m > 0; m >>= 1) s += __shfl_xor_sync(0xffffffffu, s, m);
    if (lane == 0) {
        g_sq[row] = s;
        g_ap[row] = 0u;
        g_an[row] = 0x7f800000u;
    }

    __nv_bfloat16 h0 = __float2bfloat16(v.x), h1 = __float2bfloat16(v.y);
    __nv_bfloat16 h2 = __float2bfloat16(v.z), h3 = __float2bfloat16(v.w);
    __nv_bfloat16 l0 = __float2bfloat16(v.x - __bfloat162float(h0));
    __nv_bfloat16 l1 = __float2bfloat16(v.y - __bfloat162float(h1));
    __nv_bfloat16 l2 = __float2bfloat16(v.z - __bfloat162float(h2));
    __nv_bfloat16 l3 = __float2bfloat16(v.w - __bfloat162float(h3));

    uint2 hp, lp;
    hp.x = ((unsigned)__bfloat16_as_ushort(h1) << 16) | __bfloat16_as_ushort(h0);
    hp.y = ((unsigned)__bfloat16_as_ushort(h3) << 16) | __bfloat16_as_ushort(h2);
    lp.x = ((unsigned)__bfloat16_as_ushort(l1) << 16) | __bfloat16_as_ushort(l0);
    lp.y = ((unsigned)__bfloat16_as_ushort(l3) << 16) | __bfloat16_as_ushort(l2);

    int tile = row >> 7, r = row & 127;
    int kh = (k4 >= 64) ? 1 : 0;
    int kb = (k4 & 63) * 2;
    size_t base = ((size_t)tile * 2 + kh) * SUB + sub_off(r, kb);
    *reinterpret_cast<uint2*>(g_H_img + base) = hp;
    *reinterpret_cast<uint2*>(g_L_img + base) = lp;
}

// ---------------------------------------------------------------------------
// Kernel 2: persistent triangle HMMA Gram + dual-sided fused epilogue.
// 148 CTAs x 256 thr. Units = upper-triangular 128x128 tiles (2080), stride
// distributed. 3-stage ring of 64KB khalf stages via cp.async.bulk+mbarrier.
// Warp grid 4(m) x 2(n), 32x64 per warp. Terms: HH + HL + LH.
// ---------------------------------------------------------------------------
__global__ __launch_bounds__(256) void gram_kernel() {
    extern __shared__ __align__(128) unsigned char dsm[];
    __shared__ __align__(8) unsigned long long s_full[NSTG], s_empty[NSTG];
    __shared__ float s_sqr[128], s_sqc[128];
    __shared__ int   s_clsr[128], s_clsc[128];

    const int tid = threadIdx.x, lane = tid & 31, w = tid >> 5;
    const int warp_m = w & 3, warp_n = w >> 2;
    const int bid = blockIdx.x;
    const unsigned sbase = smem_u32(dsm);

    if (tid == 0) {
        #pragma unroll
        for (int s = 0; s < NSTG; s++) {
            mbar_init(smem_u32(&s_full[s]), 1);
            mbar_init(smem_u32(&s_empty[s]), 8);
        }
    }
    __syncthreads();

    unsigned mbf[NSTG], mbe[NSTG];
    #pragma unroll
    for (int s = 0; s < NSTG; s++) { mbf[s] = smem_u32(&s_full[s]); mbe[s] = smem_u32(&s_empty[s]); }
    unsigned phf[NSTG] = {0, 0, 0}, phe[NSTG] = {0, 0, 0};

    const int nu = 1 + (NUNITS - 1 - bid) / NCTA;   // units for this CTA
    const int total_g = nu * 2;

    auto issue = [&](int g2) {
        int ord = g2 >> 1, kh = g2 & 1;
        int u = bid + ord * NCTA;
        int ti2 = 0, rem = u;
        while (rem >= NTILE - ti2) { rem -= NTILE - ti2; ti2++; }
        int tj2 = ti2 + rem;
        int st = g2 % NSTG;
        unsigned dst = sbase + (unsigned)st * STAGE;
        mbar_expect_tx(mbf[st], STAGE);
        bulk_g2s(dst,          g_H_img + ((size_t)ti2 * 2 + kh) * SUB, SUB, mbf[st]);
        bulk_g2s(dst + 16384u, g_L_img + ((size_t)ti2 * 2 + kh) * SUB, SUB, mbf[st]);
        bulk_g2s(dst + 32768u, g_H_img + ((size_t)tj2 * 2 + kh) * SUB, SUB, mbf[st]);
        bulk_g2s(dst + 49152u, g_L_img + ((size_t)tj2 * 2 + kh) * SUB, SUB, mbf[st]);
    };

    if (tid == 0) {
        if (total_g > 0) issue(0);
        if (total_g > 1) issue(1);
        if (total_g > 2) issue(2);
    }

    // per-lane ldmatrix address components (rows local to tile)
    const int aR = lane & 15;
    const int aK = (lane >> 4) * 16;
    const int bN = (lane & 7) + ((lane >> 4) << 3);
    const int bK = ((lane >> 3) & 1) * 16;
    unsigned aoff[2], asw[2];
    #pragma unroll
    for (int mi = 0; mi < 2; mi++) {
        int r = warp_m * 32 + mi * 16 + aR;
        aoff[mi] = (unsigned)r * 128u;
        asw[mi]  = ((unsigned)r & 7u) << 4;
    }
    unsigned boff[4], bsw[4];
    #pragma unroll
    for (int p = 0; p < 4; p++) {
        int r = warp_n * 64 + p * 16 + bN;
        boff[p] = (unsigned)r * 128u;
        bsw[p]  = ((unsigned)r & 7u) << 4;
    }
    const int qr = lane >> 2;
    const int qc = (lane & 3) * 2;

    float acc[2][8][4];
    int ti = 0, tj = 0;

    for (int g = 0; g < total_g; ++g) {
        const int st = g % NSTG;
        const int kh = g & 1;

        if (kh == 0) {
            // decode current unit; stage row/col stats
            int u = bid + (g >> 1) * NCTA;
            int t0 = 0, rem = u;
            while (rem >= NTILE - t0) { rem -= NTILE - t0; t0++; }
            ti = t0; tj = t0 + rem;
            __syncthreads();   // prior unit's epilogue done reading stats
            {
                int tloc = tid & 127;
                int gi = ((tid < 128) ? ti : tj) * 128 + tloc;
                if (tid < 128) { s_sqr[tloc] = g_sq[gi]; s_clsr[tloc] = g_cls[gi]; }
                else           { s_sqc[tloc] = g_sq[gi]; s_clsc[tloc] = g_cls[gi]; }
            }
            __syncthreads();   // stats visible to all warps
            #pragma unroll
            for (int mi = 0; mi < 2; mi++)
                #pragma unroll
                for (int ni = 0; ni < 8; ni++)
                    #pragma unroll
                    for (int x = 0; x < 4; x++) acc[mi][ni][x] = 0.0f;
        }

        mbar_wait(mbf[st], phf[st]); phf[st] ^= 1;

        const unsigned AH = sbase + (unsigned)st * STAGE;
        const unsigned AL = AH + 16384u, BH = AH + 32768u, BL = AH + 49152u;

        #pragma unroll
        for (int ks = 0; ks < 4; ++ks) {
            const unsigned kbA = (unsigned)(ks * 32 + aK);
            const unsigned kbB = (unsigned)(ks * 32 + bK);
            unsigned ah[2][4], al[2][4], bh[4][4], bl[4][4];
            #pragma unroll
            for (int mi = 0; mi < 2; mi++) {
                ldsm4(ah[mi], AH + aoff[mi] + (kbA ^ asw[mi]));
                ldsm4(al[mi], AL + aoff[mi] + (kbA ^ asw[mi]));
            }
            #pragma unroll
            for (int p = 0; p < 4; p++) {
                ldsm4(bh[p], BH + boff[p] + (kbB ^ bsw[p]));
                ldsm4(bl[p], BL + boff[p] + (kbB ^ bsw[p]));
            }
            #pragma unroll
            for (int mi = 0; mi < 2; mi++)
                #pragma unroll
                for (int ni = 0; ni < 8; ni++) {
                    const int p = ni >> 1, s2 = (ni & 1) * 2;
                    mma16816(acc[mi][ni], ah[mi], bh[p][s2], bh[p][s2 + 1]); // H.H
                    mma16816(acc[mi][ni], ah[mi], bl[p][s2], bl[p][s2 + 1]); // H.L
                    mma16816(acc[mi][ni], al[mi], bh[p][s2], bh[p][s2 + 1]); // L.H
                }
        }
        if (lane == 0) mbar_arrive(mbe[st]);   // stage consumed

        if (tid == 0 && g + 3 < total_g) {
            int st3 = (g + 3) % NSTG;          // == st
            mbar_wait(mbe[st3], phe[st3]); phe[st3] ^= 1;
            issue(g + 3);
        }

        if (kh == 1) {
            // ---- dual-sided epilogue ----
            const int cb = warp_n * 64;
            float cmx[8][2], cmn[8][2];
            #pragma unroll
            for (int ni = 0; ni < 8; ni++) {
                cmx[ni][0] = cmx[ni][1] = -CUDART_INF_F;
                cmn[ni][0] = cmn[ni][1] =  CUDART_INF_F;
            }
            #pragma unroll
            for (int mi = 0; mi < 2; mi++) {
                const int rl = warp_m * 32 + mi * 16 + qr;
                const int rh = rl + 8;
                const float sql = s_sqr[rl], sqh = s_sqr[rh];
                const int crl = s_clsr[rl], crh = s_clsr[rh];
                float apl = -CUDART_INF_F, anl = CUDART_INF_F;
                float aph = -CUDART_INF_F, anh = CUDART_INF_F;
                #pragma unroll
                for (int ni = 0; ni < 8; ni++) {
                    const int c0 = cb + ni * 8 + qc, c1 = c0 + 1;
                    const float sc0 = s_sqc[c0], sc1 = s_sqc[c1];
                    const int k0 = s_clsc[c0], k1 = s_clsc[c1];
                    const float d00 = acc[mi][ni][0], d01 = acc[mi][ni][1];
                    const float d10 = acc[mi][ni][2], d11 = acc[mi][ni][3];
                    const bool m0l = (k0 == crl), m1l = (k1 == crl);
                    const bool m0h = (k0 == crh), m1h = (k1 == crh);
                    // row-side partials: (sq_c - 2 dot)
                    const float r00 = fmaf(-2.0f, d00, sc0), r01 = fmaf(-2.0f, d01, sc1);
                    const float r10 = fmaf(-2.0f, d10, sc0), r11 = fmaf(-2.0f, d11, sc1);
                    apl = fmaxf(apl, m0l ? r00 : -CUDART_INF_F);
                    apl = fmaxf(apl, m1l ? r01 : -CUDART_INF_F);
                    anl = fminf(anl, m0l ? CUDART_INF_F : r00);
                    anl = fminf(anl, m1l ? CUDART_INF_F : r01);
                    aph = fmaxf(aph, m0h ? r10 : -CUDART_INF_F);
                    aph = fmaxf(aph, m1h ? r11 : -CUDART_INF_F);
                    anh = fminf(anh, m0h ? CUDART_INF_F : r10);
                    anh = fminf(anh, m1h ? CUDART_INF_F : r11);
                    // col-side partials: (sq_r - 2 dot)
                    const float q00 = fmaf(-2.0f, d00, sql), q01 = fmaf(-2.0f, d01, sql);
                    const float q10 = fmaf(-2.0f, d10, sqh), q11 = fmaf(-2.0f, d11, sqh);
                    cmx[ni][0] = fmaxf(cmx[ni][0], m0l ? q00 : -CUDART_INF_F);
                    cmx[ni][0] = fmaxf(cmx[ni][0], m0h ? q10 : -CUDART_INF_F);
                    cmx[ni][1] = fmaxf(cmx[ni][1], m1l ? q01 : -CUDART_INF_F);
                    cmx[ni][1] = fmaxf(cmx[ni][1], m1h ? q11 : -CUDART_INF_F);
                    cmn[ni][0] = fminf(cmn[ni][0], m0l ? CUDART_INF_F : q00);
                    cmn[ni][0] = fminf(cmn[ni][0], m0h ? CUDART_INF_F : q10);
                    cmn[ni][1] = fminf(cmn[ni][1], m1l ? CUDART_INF_F : q01);
                    cmn[ni][1] = fminf(cmn[ni][1], m1h ? CUDART_INF_F : q11);
                }
                #pragma unroll
                for (int m = 1; m < 4; m <<= 1) {
                    apl = fmaxf(apl, __shfl_xor_sync(0xffffffffu, apl, m));
                    anl = fminf(anl, __shfl_xor_sync(0xffffffffu, anl, m));
                    aph = fmaxf(aph, __shfl_xor_sync(0xffffffffu, aph, m));
                    anh = fminf(anh, __shfl_xor_sync(0xffffffffu, anh, m));
                }
                if ((lane & 3) == 0) {
                    const int grl = ti * 128 + rl, grh = ti * 128 + rh;
                    atomicMax(&g_ap[grl], __float_as_uint(fmaxf(sql + apl, 1e-12f)));
                    atomicMin(&g_an[grl], __float_as_uint(fmaxf(sql + anl, 1e-12f)));
                    atomicMax(&g_ap[grh], __float_as_uint(fmaxf(sqh + aph, 1e-12f)));
                    atomicMin(&g_an[grh], __float_as_uint(fmaxf(sqh + anh, 1e-12f)));
                }
            }
            // column-side: reduce over the warp's 32 rows (lanes differing in qr)
            #pragma unroll
            for (int ni = 0; ni < 8; ni++)
                #pragma unroll
                for (int j = 0; j < 2; j++)
                    #pragma unroll
                    for (int m = 4; m < 32; m <<= 1) {
                        cmx[ni][j] = fmaxf(cmx[ni][j], __shfl_xor_sync(0xffffffffu, cmx[ni][j], m));
                        cmn[ni][j] = fminf(cmn[ni][j], __shfl_xor_sync(0xffffffffu, cmn[ni][j], m));
                    }
            if (qr == 0) {   // lanes 0..3
                #pragma unroll
                for (int ni = 0; ni < 8; ni++)
                    #pragma unroll
                    for (int j = 0; j < 2; j++) {
                        const int c = cb + ni * 8 + (lane & 3) * 2 + j;
                        const int gc = tj * 128 + c;
                        const float sc = s_sqc[c];
                        atomicMax(&g_ap[gc], __float_as_uint(fmaxf(cmx[ni][j] + sc, 1e-12f)));
                        atomicMin(&g_an[gc], __float_as_uint(fmaxf(cmn[ni][j] + sc, 1e-12f)));
                    }
            }
        }
    }
}

// ---------------------------------------------------------------------------
// Kernel 3: per-row confusion + partial sums. 32 blocks x 256.
// ---------------------------------------------------------------------------
__global__ void confuse_kernel(const float* __restrict__ pred) {
    __shared__ float s_s[8], s_c[8];
    int i = blockIdx.x * 256 + threadIdx.x;

    const float* pr = pred + (size_t)i * NCLS;
    float l[NCLS];
    float mx = -CUDART_INF_F;
    #pragma unroll
    for (int c = 0; c < NCLS; c++) { l[c] = pr[c]; mx = fmaxf(mx, l[c]); }
    float s = 0.0f;
    #pragma unroll
    for (int c = 0; c < NCLS; c++) { l[c] = __expf(l[c] - mx); s += l[c]; }
    float inv = 1.0f / s;
    float v1 = -1.0f, v2 = -1.0f;
    int i1 = 0;
    #pragma unroll
    for (int c = 0; c < NCLS; c++) {
        float p = l[c] * inv;
        if (p > v1) { v2 = v1; v1 = p; i1 = c; }
        else if (p > v2) { v2 = p; }
    }
    bool confuse = ((v1 - v2) <= GAPV) || (i1 != g_cls[i]);

    float ap = sqrtf(__uint_as_float(g_ap[i]));
    float an = sqrtf(__uint_as_float(g_an[i]));
    float per = fmaxf(ap - an, 0.0f);
    float sum = confuse ? per : 0.0f;
    float cnt = confuse ? 1.0f : 0.0f;

    #pragma unroll
    for (int m = 16; m > 0; m >>= 1) {
        sum += __shfl_xor_sync(0xffffffffu, sum, m);
        cnt += __shfl_xor_sync(0xffffffffu, cnt, m);
    }
    int wid = threadIdx.x >> 5, lane = threadIdx.x & 31;
    if (lane == 0) { s_s[wid] = sum; s_c[wid] = cnt; }
    __syncthreads();
    if (threadIdx.x == 0) {
        float ts = 0.0f, tc = 0.0f;
        #pragma unroll
        for (int w2 = 0; w2 < 8; w2++) { ts += s_s[w2]; tc += s_c[w2]; }
        g_part[blockIdx.x * 2]     = ts;
        g_part[blockIdx.x * 2 + 1] = tc;
    }
}

__global__ void final_kernel(float* __restrict__ out) {
    float s = 0.0f, c = 0.0f;
    #pragma unroll
    for (int b = 0; b < 32; b++) { s += g_part[b * 2]; c += g_part[b * 2 + 1]; }
    out[0] = (c > 0.0f) ? (s / c) : 0.0f;
}

// ---------------------------------------------------------------------------
extern "C" void kernel_launch(void* const* d_in, const int* in_sizes, int n_in,
                              void* d_out, int out_size) {
    const float* X    = (const float*)d_in[0];
    const float* pred = (const float*)d_in[1];
    const int*   tgt  = (const int*)d_in[2];
    float* out = (float*)d_out;

    static int smem_set = 0;
    const int SMEM_DYN = NSTG * STAGE;   // 196608
    if (!smem_set) {
        cudaFuncSetAttribute(gram_kernel,
                             cudaFuncAttributeMaxDynamicSharedMemorySize, SMEM_DYN);
        smem_set = 1;
    }

    classes_kernel<<<8, 1024>>>(tgt);
    convert_kernel<<<NROWS / 8, 256>>>(X);
    gram_kernel<<<NCTA, 256, SMEM_DYN>>>();
    confuse_kernel<<<32, 256>>>(pred);
    final_kernel<<<1, 1>>>(out);
}